// round 8
// baseline (speedup 1.0000x reference)
#include <cuda_runtime.h>
#include <math.h>
#include <stdint.h>

// ---------------- problem constants ----------------
#define Bsz   4
#define Ssz   2048
#define Esz   1024
#define Hsz   8
#define Mrows (Bsz * Ssz)          // 8192
#define N_UVQK 4096
#define N_PROJ 3072
#define ALPHA_SC 0.08838834764831845f   // 1/sqrt(128)
#define INV_S    (1.0f / 2048.0f)
#define LN_EPS   1e-6f

// ---------------- scratch (device globals; no allocation allowed) ----------------
__device__ float g_normx[(size_t)Mrows * Esz];    // 32 MB
__device__ float g_uvqk [(size_t)Mrows * N_UVQK]; // 128 MB
__device__ float g_attn [(size_t)Mrows * Esz];    // 32 MB
__device__ float g_proj [(size_t)Mrows * N_PROJ]; // 96 MB

// ---------------- helpers ----------------
__device__ __forceinline__ uint32_t f2tf32(float x) {
    uint32_t r;
    asm("cvt.rna.tf32.f32 %0, %1;" : "=r"(r) : "f"(x));
    return r;
}

__device__ __forceinline__ void mma_tf32(float* d,
    uint32_t a0, uint32_t a1, uint32_t a2, uint32_t a3,
    uint32_t b0, uint32_t b1)
{
    asm volatile(
        "mma.sync.aligned.m16n8k8.row.col.f32.tf32.tf32.f32 "
        "{%0,%1,%2,%3}, {%4,%5,%6,%7}, {%8,%9}, {%0,%1,%2,%3};\n"
        : "+f"(d[0]), "+f"(d[1]), "+f"(d[2]), "+f"(d[3])
        : "r"(a0), "r"(a1), "r"(a2), "r"(a3), "r"(b0), "r"(b1));
}

__device__ __forceinline__ float silu_f(float x) {
    return x / (1.0f + expf(-x));
}

__device__ __forceinline__ void blockReduce2(float& a, float& b) {
    #pragma unroll
    for (int off = 16; off > 0; off >>= 1) {
        a += __shfl_down_sync(0xffffffffu, a, off);
        b += __shfl_down_sync(0xffffffffu, b, off);
    }
    __shared__ float sa[8], sb[8];
    __shared__ float ra, rb;
    int w = threadIdx.x >> 5, l = threadIdx.x & 31;
    if (l == 0) { sa[w] = a; sb[w] = b; }
    __syncthreads();
    if (threadIdx.x == 0) {
        float ta = 0.f, tb = 0.f;
        #pragma unroll
        for (int i = 0; i < 8; i++) { ta += sa[i]; tb += sb[i]; }
        ra = ta; rb = tb;
    }
    __syncthreads();
    a = ra; b = rb;
}

// ---------------- LayerNorm on input x -> g_normx ----------------
__global__ __launch_bounds__(256) void ln_in_kernel(
    const float* __restrict__ x, const float* __restrict__ sc,
    const float* __restrict__ bi, float* __restrict__ out)
{
    int row = blockIdx.x;
    int c = threadIdx.x * 4;
    const float* xr = x + (size_t)row * Esz;
    float4 v = *(const float4*)&xr[c];
    float s  = v.x + v.y + v.z + v.w;
    float ss = v.x*v.x + v.y*v.y + v.z*v.z + v.w*v.w;
    blockReduce2(s, ss);
    float mu = s * (1.0f / Esz);
    float rs = rsqrtf(ss * (1.0f / Esz) - mu * mu + LN_EPS);
    float4 s4 = *(const float4*)&sc[c];
    float4 b4 = *(const float4*)&bi[c];
    float4 o;
    o.x = (v.x - mu) * rs * s4.x + b4.x;
    o.y = (v.y - mu) * rs * s4.y + b4.y;
    o.z = (v.z - mu) * rs * s4.z + b4.z;
    o.w = (v.w - mu) * rs * s4.w + b4.w;
    *(float4*)&out[(size_t)row * Esz + c] = o;
}

// ---------------- tf32 mma.sync GEMM, double-buffered, 2 CTAs/SM -----------
// A: MxK row-major fp32. B: KxN row-major fp32. Block tile 128x128, kTile 16.
// 8 warps in 2(M) x 4(N): warp tile 64x32 via m16n8k8. 2-stage smem pipeline.
// If silu_dst != null: for columns < 1024 also write silu(v) to
// silu_dst[row * N_PROJ + col]  (fuses the u -> silu(u) pass of GEMM1).
__global__ __launch_bounds__(256, 2) void gemm_tf32_kernel(
    const float* __restrict__ A, const float* __restrict__ Bm,
    float* __restrict__ C, int M, int N, int K,
    const float* __restrict__ bias, const float* __restrict__ resid,
    float* __restrict__ silu_dst)
{
    __shared__ uint32_t As[2][16][132];   // [stage][k][m] (transposed)
    __shared__ uint32_t Bs[2][16][132];   // [stage][k][n]

    int tid = threadIdx.x;
    int wid = tid >> 5, lane = tid & 31;
    int gID = lane >> 2, tig = lane & 3;
    int warpM = wid & 1, warpN = wid >> 1;
    int bx = blockIdx.x, by = blockIdx.y;

    int arow = tid >> 1, acol = (tid & 1) * 8;
    int brow = tid >> 4, bcol = (tid & 15) * 8;
    const float* Aload = A + (size_t)(by * 128 + arow) * K + acol;
    const float* Bload = Bm + (size_t)brow * N + bx * 128 + bcol;

    float acc[4][4][4];
    #pragma unroll
    for (int i = 0; i < 4; i++)
        #pragma unroll
        for (int j = 0; j < 4; j++)
            #pragma unroll
            for (int q = 0; q < 4; q++) acc[i][j][q] = 0.f;

    float4 pa0, pa1, pb0, pb1;
    pa0 = *(const float4*)Aload;       pa1 = *(const float4*)(Aload + 4);
    pb0 = *(const float4*)Bload;       pb1 = *(const float4*)(Bload + 4);

    auto store_tiles = [&](int st) {
        As[st][acol + 0][arow] = f2tf32(pa0.x);
        As[st][acol + 1][arow] = f2tf32(pa0.y);
        As[st][acol + 2][arow] = f2tf32(pa0.z);
        As[st][acol + 3][arow] = f2tf32(pa0.w);
        As[st][acol + 4][arow] = f2tf32(pa1.x);
        As[st][acol + 5][arow] = f2tf32(pa1.y);
        As[st][acol + 6][arow] = f2tf32(pa1.z);
        As[st][acol + 7][arow] = f2tf32(pa1.w);
        Bs[st][brow][bcol + 0] = f2tf32(pb0.x);
        Bs[st][brow][bcol + 1] = f2tf32(pb0.y);
        Bs[st][brow][bcol + 2] = f2tf32(pb0.z);
        Bs[st][brow][bcol + 3] = f2tf32(pb0.w);
        Bs[st][brow][bcol + 4] = f2tf32(pb1.x);
        Bs[st][brow][bcol + 5] = f2tf32(pb1.y);
        Bs[st][brow][bcol + 6] = f2tf32(pb1.z);
        Bs[st][brow][bcol + 7] = f2tf32(pb1.w);
    };

    store_tiles(0);
    __syncthreads();

    int s = 0;
    for (int k0 = 0; k0 < K; k0 += 16) {
        bool more = (k0 + 16) < K;
        if (more) {
            Aload += 16;
            Bload += (size_t)16 * N;
            pa0 = *(const float4*)Aload;  pa1 = *(const float4*)(Aload + 4);
            pb0 = *(const float4*)Bload;  pb1 = *(const float4*)(Bload + 4);
        }
        #pragma unroll
        for (int ks = 0; ks < 2; ks++) {
            int kb = ks * 8;
            uint32_t af[4][4], bf[4][2];
            #pragma unroll
            for (int i = 0; i < 4; i++) {
                int m = warpM * 64 + i * 16 + gID;
                af[i][0] = As[s][kb + tig][m];
                af[i][1] = As[s][kb + tig][m + 8];
                af[i][2] = As[s][kb + tig + 4][m];
                af[i][3] = As[s][kb + tig + 4][m + 8];
            }
            #pragma unroll
            for (int j = 0; j < 4; j++) {
                int n = warpN * 32 + j * 8 + gID;
                bf[j][0] = Bs[s][kb + tig][n];
                bf[j][1] = Bs[s][kb + tig + 4][n];
            }
            #pragma unroll
            for (int i = 0; i < 4; i++)
                #pragma unroll
                for (int j = 0; j < 4; j++)
                    mma_tf32(acc[i][j], af[i][0], af[i][1], af[i][2], af[i][3],
                             bf[j][0], bf[j][1]);
        }
        if (more) {
            store_tiles(s ^ 1);
            __syncthreads();
            s ^= 1;
        }
    }

    // epilogue
    bool siluTile = (silu_dst != nullptr) && (bx * 128 < 1024);
    #pragma unroll
    for (int i = 0; i < 4; i++) {
        int r0 = by * 128 + warpM * 64 + i * 16 + gID;
        #pragma unroll
        for (int j = 0; j < 4; j++) {
            int cg = bx * 128 + warpN * 32 + j * 8 + tig * 2;
            float v0 = acc[i][j][0], v1 = acc[i][j][1];
            float v2 = acc[i][j][2], v3 = acc[i][j][3];
            if (bias) {
                float b0 = bias[cg], b1 = bias[cg + 1];
                v0 += b0; v1 += b1; v2 += b0; v3 += b1;
            }
            size_t o0 = (size_t)r0 * N + cg;
            size_t o1 = (size_t)(r0 + 8) * N + cg;
            if (resid) {
                v0 += resid[o0]; v1 += resid[o0 + 1];
                v2 += resid[o1]; v3 += resid[o1 + 1];
            }
            *(float2*)&C[o0] = make_float2(v0, v1);
            *(float2*)&C[o1] = make_float2(v2, v3);
            if (siluTile) {
                size_t p0 = (size_t)r0 * N_PROJ + cg;
                size_t p1 = (size_t)(r0 + 8) * N_PROJ + cg;
                *(float2*)&silu_dst[p0] = make_float2(silu_f(v0), silu_f(v1));
                *(float2*)&silu_dst[p1] = make_float2(silu_f(v2), silu_f(v3));
            }
        }
    }
}

// ---------------- tensor-core fused attention (mma.sync, causal-skip) -------
// block = (b, h, 32 q rows). 256 threads / 8 warps. K-tiles of 64.
//   S = Q @ K^T (32x64x128) -> mask/silu -> Ws -> O += Ws @ V (32x128x64)
// smem words: Qs[32][132]@0  Ks[64][132]@4224  Vs[64][132]@12672  Ws[32][68]@21120
// total 23296 words = 93184 B  -> 2 CTAs/SM
#define QS(r,c) sm[(r) * 132 + (c)]
#define KS(r,c) sm[4224 + (r) * 132 + (c)]
#define VS(r,c) sm[12672 + (r) * 132 + (c)]
#define WS(r,c) sm[21120 + (r) * 68 + (c)]
#define ATTN_SMEM_BYTES (23296 * 4)

__global__ __launch_bounds__(256, 2) void attn_tc_kernel(
    const float* __restrict__ uvqk, const int* __restrict__ num_targets,
    float* __restrict__ attn_out)
{
    extern __shared__ uint32_t sm[];
    int tid = threadIdx.x;
    int wid = tid >> 5, lane = tid & 31;
    int gID = lane >> 2, tig = lane & 3;
    int b = blockIdx.z, h = blockIdx.y;
    int q0 = blockIdx.x * 32;
    int maxid = Ssz - num_targets[b];

    const size_t rstride = N_UVQK;
    const float* qbase = uvqk + (size_t)(b * Ssz) * rstride + 2048 + h * 128;
    const float* kbase = uvqk + (size_t)(b * Ssz) * rstride + 3072 + h * 128;
    const float* vbase = uvqk + (size_t)(b * Ssz) * rstride + 1024 + h * 128;

    // load Q tile (32 x 128): 8 threads per row, 16 floats each
    {
        int r = tid >> 3, cb = (tid & 7) * 16;
        const float* src = qbase + (size_t)(q0 + r) * rstride + cb;
        #pragma unroll
        for (int x = 0; x < 4; x++) {
            float4 v = *(const float4*)(src + x * 4);
            QS(r, cb + x * 4 + 0) = f2tf32(v.x);
            QS(r, cb + x * 4 + 1) = f2tf32(v.y);
            QS(r, cb + x * 4 + 2) = f2tf32(v.z);
            QS(r, cb + x * 4 + 3) = f2tf32(v.w);
        }
    }

    // score warps: 2(M:16) x 4(N:16); output warps: 2(M:16) x 4(N:32)
    int sWM = wid & 1, sWN = wid >> 1;
    int oWM = wid & 1, oWN = wid >> 1;

    float acc_o[4][4];
    #pragma unroll
    for (int j = 0; j < 4; j++)
        #pragma unroll
        for (int q = 0; q < 4; q++) acc_o[j][q] = 0.f;

    int ldr = tid >> 2, ldc = (tid & 3) * 32;

    // mask is zero for all k > q: only k0 <= q0 tiles contribute
    for (int k0 = 0; k0 <= q0; k0 += 64) {
        __syncthreads();   // previous iteration's reads of Ks/Vs/Ws (and Qs load) done
        // load K and V tiles (64 x 128 each)
        {
            const float* ksrc = kbase + (size_t)(k0 + ldr) * rstride + ldc;
            const float* vsrc = vbase + (size_t)(k0 + ldr) * rstride + ldc;
            #pragma unroll
            for (int x = 0; x < 8; x++) {
                float4 kv = *(const float4*)(ksrc + x * 4);
                KS(ldr, ldc + x * 4 + 0) = f2tf32(kv.x);
                KS(ldr, ldc + x * 4 + 1) = f2tf32(kv.y);
                KS(ldr, ldc + x * 4 + 2) = f2tf32(kv.z);
                KS(ldr, ldc + x * 4 + 3) = f2tf32(kv.w);
            }
            #pragma unroll
            for (int x = 0; x < 8; x++) {
                float4 vv = *(const float4*)(vsrc + x * 4);
                VS(ldr, ldc + x * 4 + 0) = f2tf32(vv.x);
                VS(ldr, ldc + x * 4 + 1) = f2tf32(vv.y);
                VS(ldr, ldc + x * 4 + 2) = f2tf32(vv.z);
                VS(ldr, ldc + x * 4 + 3) = f2tf32(vv.w);
            }
        }
        __syncthreads();

        // scores: S(32x64) = Q(32x128) @ K^T ; per warp 16x16 (2 n8 mmas)
        float acc_s[2][4];
        #pragma unroll
        for (int j = 0; j < 2; j++)
            #pragma unroll
            for (int q = 0; q < 4; q++) acc_s[j][q] = 0.f;

        #pragma unroll
        for (int ks = 0; ks < 16; ks++) {
            int kb = ks * 8;
            int m = sWM * 16 + gID;
            uint32_t a0 = QS(m, kb + tig);
            uint32_t a1 = QS(m + 8, kb + tig);
            uint32_t a2 = QS(m, kb + tig + 4);
            uint32_t a3 = QS(m + 8, kb + tig + 4);
            #pragma unroll
            for (int j = 0; j < 2; j++) {
                int n = sWN * 16 + j * 8 + gID;
                uint32_t b0 = KS(n, kb + tig);
                uint32_t b1 = KS(n, kb + tig + 4);
                mma_tf32(acc_s[j], a0, a1, a2, a3, b0, b1);
            }
        }

        // mask + silu -> Ws
        {
            int rowL = sWM * 16 + gID;
            int qg0 = q0 + rowL;
            int qg1 = qg0 + 8;
            int idq0 = min(qg0, maxid);
            int idq1 = min(qg1, maxid);
            #pragma unroll
            for (int j = 0; j < 2; j++) {
                int colL = sWN * 16 + j * 8 + tig * 2;
                #pragma unroll
                for (int cc = 0; cc < 2; cc++) {
                    int kg = k0 + colL + cc;
                    int idk = min(kg, maxid);
                    float s0 = acc_s[j][cc] * ALPHA_SC;
                    float s1 = acc_s[j][cc + 2] * ALPHA_SC;
                    bool v0 = (qg0 == kg) || (idq0 > idk);
                    bool v1 = (qg1 == kg) || (idq1 > idk);
                    float w0 = v0 ? silu_f(s0) * INV_S : 0.f;
                    float w1 = v1 ? silu_f(s1) * INV_S : 0.f;
                    WS(rowL, colL + cc)     = f2tf32(w0);
                    WS(rowL + 8, colL + cc) = f2tf32(w1);
                }
            }
        }
        __syncthreads();

        // O += Ws(32x64) @ V(64x128) ; per warp 16x32 (4 n8 mmas)
        #pragma unroll
        for (int ks = 0; ks < 8; ks++) {
            int kb = ks * 8;
            int m = oWM * 16 + gID;
            uint32_t af0 = WS(m, kb + tig);
            uint32_t af1 = WS(m + 8, kb + tig);
            uint32_t af2 = WS(m, kb + tig + 4);
            uint32_t af3 = WS(m + 8, kb + tig + 4);
            #pragma unroll
            for (int j = 0; j < 4; j++) {
                int n = oWN * 32 + j * 8 + gID;
                uint32_t b0 = VS(kb + tig, n);
                uint32_t b1 = VS(kb + tig + 4, n);
                mma_tf32(acc_o[j], af0, af1, af2, af3, b0, b1);
            }
        }
    }

    // epilogue
    {
        int rowL = oWM * 16 + gID;
        size_t grow0 = (size_t)(b * Ssz + q0 + rowL) * Esz;
        size_t grow1 = (size_t)(b * Ssz + q0 + rowL + 8) * Esz;
        #pragma unroll
        for (int j = 0; j < 4; j++) {
            int col = h * 128 + oWN * 32 + j * 8 + tig * 2;
            *(float2*)&attn_out[grow0 + col] = make_float2(acc_o[j][0], acc_o[j][1]);
            *(float2*)&attn_out[grow1 + col] = make_float2(acc_o[j][2], acc_o[j][3]);
        }
    }
}

// ---------------- post-attention: LN(attn), gate, fill proj ----------------
__global__ __launch_bounds__(256) void postattn_kernel(
    const float* __restrict__ attn, const float* __restrict__ sc,
    const float* __restrict__ bi, float* __restrict__ proj)
{
    int row = blockIdx.x;
    int c = threadIdx.x * 4;
    const float* ar = attn + (size_t)row * Esz;
    float4 a = *(const float4*)&ar[c];
    float s  = a.x + a.y + a.z + a.w;
    float ss = a.x*a.x + a.y*a.y + a.z*a.z + a.w*a.w;
    blockReduce2(s, ss);
    float mu = s * (1.0f / Esz);
    float rs = rsqrtf(ss * (1.0f / Esz) - mu * mu + LN_EPS);
    float4 s4 = *(const float4*)&sc[c];
    float4 b4 = *(const float4*)&bi[c];
    float4 n;
    n.x = (a.x - mu) * rs * s4.x + b4.x;
    n.y = (a.y - mu) * rs * s4.y + b4.y;
    n.z = (a.z - mu) * rs * s4.z + b4.z;
    n.w = (a.w - mu) * rs * s4.w + b4.w;
    float* pr = proj + (size_t)row * N_PROJ;
    float4 u = *(const float4*)&pr[c];
    *(float4*)&pr[1024 + c] = a;
    float4 g;
    g.x = u.x * n.x; g.y = u.y * n.y; g.z = u.z * n.z; g.w = u.w * n.w;
    *(float4*)&pr[2048 + c] = g;
}

// ---------------- launch ----------------
extern "C" void kernel_launch(void* const* d_in, const int* in_sizes, int n_in,
                              void* d_out, int out_size)
{
    const float* x           = (const float*)d_in[0];
    const int*   num_targets = (const int*)  d_in[1];
    const float* uvqk_w      = (const float*)d_in[2];
    const float* uvqk_beta   = (const float*)d_in[3];
    const float* out_w       = (const float*)d_in[4];
    const float* in_scale    = (const float*)d_in[5];
    const float* in_bias     = (const float*)d_in[6];
    const float* out_scale   = (const float*)d_in[7];
    const float* out_bias    = (const float*)d_in[8];
    float* out = (float*)d_out;

    float *normx, *uvqk, *attn, *proj;
    cudaGetSymbolAddress((void**)&normx, g_normx);
    cudaGetSymbolAddress((void**)&uvqk,  g_uvqk);
    cudaGetSymbolAddress((void**)&attn,  g_attn);
    cudaGetSymbolAddress((void**)&proj,  g_proj);

    // idempotent, capture-safe; no static state
    cudaFuncSetAttribute(attn_tc_kernel,
                         cudaFuncAttributeMaxDynamicSharedMemorySize,
                         ATTN_SMEM_BYTES);

    // 1) LayerNorm input
    ln_in_kernel<<<Mrows, 256>>>(x, in_scale, in_bias, normx);

    // 2) UVQK GEMM: (8192 x 1024) @ (1024 x 4096) + beta, silu(u) tap
    gemm_tf32_kernel<<<dim3(N_UVQK / 128, Mrows / 128), 256>>>(
        normx, uvqk_w, uvqk, Mrows, N_UVQK, Esz, uvqk_beta, nullptr, proj);

    // 3) tensor-core attention (causal-skip, 32-row q tiles) -> attn
    attn_tc_kernel<<<dim3(Ssz / 32, Hsz, Bsz), 256, ATTN_SMEM_BYTES>>>(
        uvqk, num_targets, attn);

    // 4) LN(attn) + gate
    postattn_kernel<<<Mrows, 256>>>(attn, out_scale, out_bias, proj);

    // 5) output GEMM with fused residual
    gemm_tf32_kernel<<<dim3(Esz / 128, Mrows / 128), 256>>>(
        proj, out_w, out, Mrows, Esz, N_PROJ, nullptr, x, nullptr);
}

// round 10
// speedup vs baseline: 1.3317x; 1.3317x over previous
#include <cuda_runtime.h>
#include <math.h>
#include <stdint.h>

// ---------------- problem constants ----------------
#define Bsz   4
#define Ssz   2048
#define Esz   1024
#define Hsz   8
#define Mrows (Bsz * Ssz)          // 8192
#define N_UVQK 4096
#define N_PROJ 3072
#define ALPHA_SC 0.08838834764831845f   // 1/sqrt(128)
#define INV_S    (1.0f / 2048.0f)
#define LN_EPS   1e-6f

// ---------------- scratch (device globals; no allocation allowed) -----------
__device__ float g_normx[(size_t)Mrows * Esz];    // 32 MB (tf32-rounded)
__device__ float g_uvqk [(size_t)Mrows * N_UVQK]; // 128 MB (full fp32)
__device__ float g_attn [(size_t)Mrows * Esz];    // 32 MB (full fp32)
__device__ float g_proj [(size_t)Mrows * N_PROJ]; // 96 MB (tf32-rounded)
__device__ float g_w1   [(size_t)Esz * N_UVQK];   // 16 MB rounded uvqk_w
__device__ float g_w2   [(size_t)N_PROJ * Esz];   // 12 MB rounded out_w

// ---------------- helpers ----------------
__device__ __forceinline__ uint32_t f2tf32(float x) {
    uint32_t r;
    asm("cvt.rna.tf32.f32 %0, %1;" : "=r"(r) : "f"(x));
    return r;
}
__device__ __forceinline__ float rnd32(float x) {
    return __uint_as_float(f2tf32(x));
}

__device__ __forceinline__ void mma_tf32(float* d,
    uint32_t a0, uint32_t a1, uint32_t a2, uint32_t a3,
    uint32_t b0, uint32_t b1)
{
    asm volatile(
        "mma.sync.aligned.m16n8k8.row.col.f32.tf32.tf32.f32 "
        "{%0,%1,%2,%3}, {%4,%5,%6,%7}, {%8,%9}, {%0,%1,%2,%3};\n"
        : "+f"(d[0]), "+f"(d[1]), "+f"(d[2]), "+f"(d[3])
        : "r"(a0), "r"(a1), "r"(a2), "r"(a3), "r"(b0), "r"(b1));
}

__device__ __forceinline__ float silu_f(float x) {
    return x / (1.0f + expf(-x));
}

__device__ __forceinline__ uint32_t smem_u32(const void* p) {
    uint32_t a;
    asm("{ .reg .u64 t; cvta.to.shared.u64 t, %1; cvt.u32.u64 %0, t; }"
        : "=r"(a) : "l"(p));
    return a;
}

__device__ __forceinline__ void cp_async16(uint32_t dst, const void* src) {
    asm volatile("cp.async.cg.shared.global [%0], [%1], 16;\n"
                 :: "r"(dst), "l"(src));
}
#define CP_COMMIT()  asm volatile("cp.async.commit_group;\n" ::: "memory")
#define CP_WAIT1()   asm volatile("cp.async.wait_group 1;\n" ::: "memory")

__device__ __forceinline__ void blockReduce2(float& a, float& b) {
    #pragma unroll
    for (int off = 16; off > 0; off >>= 1) {
        a += __shfl_down_sync(0xffffffffu, a, off);
        b += __shfl_down_sync(0xffffffffu, b, off);
    }
    __shared__ float sa[8], sb[8];
    __shared__ float ra, rb;
    int w = threadIdx.x >> 5, l = threadIdx.x & 31;
    if (l == 0) { sa[w] = a; sb[w] = b; }
    __syncthreads();
    if (threadIdx.x == 0) {
        float ta = 0.f, tb = 0.f;
        #pragma unroll
        for (int i = 0; i < 8; i++) { ta += sa[i]; tb += sb[i]; }
        ra = ta; rb = tb;
    }
    __syncthreads();
    a = ra; b = rb;
}

// ---------------- tf32 pre-round of weights ----------------
__global__ __launch_bounds__(256) void round_w_kernel(
    const float* __restrict__ src, float* __restrict__ dst, int n4)
{
    int i = (blockIdx.x * 256 + threadIdx.x);
    if (i < n4) {
        float4 v = *(const float4*)(src + (size_t)i * 4);
        v.x = rnd32(v.x); v.y = rnd32(v.y); v.z = rnd32(v.z); v.w = rnd32(v.w);
        *(float4*)(dst + (size_t)i * 4) = v;
    }
}

// ---------------- LayerNorm on input x -> g_normx (tf32-rounded) -----------
__global__ __launch_bounds__(256) void ln_in_kernel(
    const float* __restrict__ x, const float* __restrict__ sc,
    const float* __restrict__ bi, float* __restrict__ out)
{
    int row = blockIdx.x;
    int c = threadIdx.x * 4;
    const float* xr = x + (size_t)row * Esz;
    float4 v = *(const float4*)&xr[c];
    float s  = v.x + v.y + v.z + v.w;
    float ss = v.x*v.x + v.y*v.y + v.z*v.z + v.w*v.w;
    blockReduce2(s, ss);
    float mu = s * (1.0f / Esz);
    float rs = rsqrtf(ss * (1.0f / Esz) - mu * mu + LN_EPS);
    float4 s4 = *(const float4*)&sc[c];
    float4 b4 = *(const float4*)&bi[c];
    float4 o;
    o.x = rnd32((v.x - mu) * rs * s4.x + b4.x);
    o.y = rnd32((v.y - mu) * rs * s4.y + b4.y);
    o.z = rnd32((v.z - mu) * rs * s4.z + b4.z);
    o.w = rnd32((v.w - mu) * rs * s4.w + b4.w);
    *(float4*)&out[(size_t)row * Esz + c] = o;
}

// ---------------- tf32 mma.sync GEMM, cp.async 3-stage ----------------------
// A: MxK row-major fp32 (values already tf32-rounded). B: KxN likewise.
// Block tile 128x128, kTile 16, 3-stage cp.async pipeline.
// smem words per stage: A[m=128][kpad=20] = 2560, B[k=16][npad=132] = 2112.
#define GSTG_WORDS 4672
#define GEMM_SMEM_BYTES (3 * GSTG_WORDS * 4)   // 56064 B

__global__ __launch_bounds__(256, 2) void gemm_tf32_kernel(
    const float* __restrict__ A, const float* __restrict__ Bm,
    float* __restrict__ C, int M, int N, int K,
    const float* __restrict__ bias, const float* __restrict__ resid,
    float* __restrict__ silu_dst)
{
    extern __shared__ __align__(16) uint32_t gsm[];
    uint32_t sbase = smem_u32(gsm);

    int tid = threadIdx.x;
    int wid = tid >> 5, lane = tid & 31;
    int gID = lane >> 2, tig = lane & 3;
    int warpM = wid & 1, warpN = wid >> 1;
    int bx = blockIdx.x, by = blockIdx.y;

    int arow = tid >> 1, acol = (tid & 1) * 8;
    int brow = tid >> 4, bcol = (tid & 15) * 8;
    const float* Abase = A + (size_t)(by * 128 + arow) * K + acol;
    const float* Bbase = Bm + (size_t)brow * N + bx * 128 + bcol;

    int nIter = K >> 4;

    auto issue_stage = [&](int c) {
        int s = c - (c / 3) * 3;
        uint32_t ab = sbase + (uint32_t)(s * GSTG_WORDS) * 4;
        uint32_t bb = ab + 2560 * 4;
        const float* ag = Abase + c * 16;
        cp_async16(ab + (uint32_t)(arow * 20 + acol) * 4, ag);
        cp_async16(ab + (uint32_t)(arow * 20 + acol + 4) * 4, ag + 4);
        const float* bg = Bbase + (size_t)(c * 16) * N;
        cp_async16(bb + (uint32_t)(brow * 132 + bcol) * 4, bg);
        cp_async16(bb + (uint32_t)(brow * 132 + bcol + 4) * 4, bg + 4);
    };

    float acc[4][4][4];
    #pragma unroll
    for (int i = 0; i < 4; i++)
        #pragma unroll
        for (int j = 0; j < 4; j++)
            #pragma unroll
            for (int q = 0; q < 4; q++) acc[i][j][q] = 0.f;

    issue_stage(0); CP_COMMIT();
    issue_stage(1); CP_COMMIT();

    for (int c = 0; c < nIter; c++) {
        CP_WAIT1();            // stage c resident
        __syncthreads();       // all warps done with stage c-1 compute; c visible
        if (c + 2 < nIter) issue_stage(c + 2);
        CP_COMMIT();           // always commit (empty group at tail keeps count)

        int s = c - (c / 3) * 3;
        const uint32_t* As = gsm + s * GSTG_WORDS;
        const uint32_t* Bs = As + 2560;
        #pragma unroll
        for (int ks = 0; ks < 2; ks++) {
            int kb = ks * 8;
            uint32_t af[4][4], bf[4][2];
            #pragma unroll
            for (int i = 0; i < 4; i++) {
                int m = warpM * 64 + i * 16 + gID;
                af[i][0] = As[m * 20 + kb + tig];
                af[i][1] = As[(m + 8) * 20 + kb + tig];
                af[i][2] = As[m * 20 + kb + tig + 4];
                af[i][3] = As[(m + 8) * 20 + kb + tig + 4];
            }
            #pragma unroll
            for (int j = 0; j < 4; j++) {
                int n = warpN * 32 + j * 8 + gID;
                bf[j][0] = Bs[(kb + tig) * 132 + n];
                bf[j][1] = Bs[(kb + tig + 4) * 132 + n];
            }
            #pragma unroll
            for (int i = 0; i < 4; i++)
                #pragma unroll
                for (int j = 0; j < 4; j++)
                    mma_tf32(acc[i][j], af[i][0], af[i][1], af[i][2], af[i][3],
                             bf[j][0], bf[j][1]);
        }
    }

    // epilogue
    bool siluTile = (silu_dst != nullptr) && (bx * 128 < 1024);
    #pragma unroll
    for (int i = 0; i < 4; i++) {
        int r0 = by * 128 + warpM * 64 + i * 16 + gID;
        #pragma unroll
        for (int j = 0; j < 4; j++) {
            int cg = bx * 128 + warpN * 32 + j * 8 + tig * 2;
            float v0 = acc[i][j][0], v1 = acc[i][j][1];
            float v2 = acc[i][j][2], v3 = acc[i][j][3];
            if (bias) {
                float b0 = bias[cg], b1 = bias[cg + 1];
                v0 += b0; v1 += b1; v2 += b0; v3 += b1;
            }
            size_t o0 = (size_t)r0 * N + cg;
            size_t o1 = (size_t)(r0 + 8) * N + cg;
            if (resid) {
                v0 += resid[o0]; v1 += resid[o0 + 1];
                v2 += resid[o1]; v3 += resid[o1 + 1];
            }
            *(float2*)&C[o0] = make_float2(v0, v1);
            *(float2*)&C[o1] = make_float2(v2, v3);
            if (siluTile) {
                size_t p0 = (size_t)r0 * N_PROJ + cg;
                size_t p1 = (size_t)(r0 + 8) * N_PROJ + cg;
                *(float2*)&silu_dst[p0] =
                    make_float2(rnd32(silu_f(v0)), rnd32(silu_f(v1)));
                *(float2*)&silu_dst[p1] =
                    make_float2(rnd32(silu_f(v2)), rnd32(silu_f(v3)));
            }
        }
    }
}

// ---------------- tensor-core fused attention (R5 configuration) ------------
// block = (b, h, 64 q rows). 256 threads / 8 warps. K-tiles of 64, causal skip.
#define QS(r,c) sm[(r) * 132 + (c)]
#define KS(r,c) sm[8448 + (r) * 132 + (c)]
#define VS(r,c) sm[16896 + (r) * 132 + (c)]
#define WS(r,c) sm[25344 + (r) * 68 + (c)]
#define ATTN_SMEM_BYTES (29696 * 4)

__global__ __launch_bounds__(256) void attn_tc_kernel(
    const float* __restrict__ uvqk, const int* __restrict__ num_targets,
    float* __restrict__ attn_out)
{
    extern __shared__ uint32_t sm[];
    int tid = threadIdx.x;
    int wid = tid >> 5, lane = tid & 31;
    int gID = lane >> 2, tig = lane & 3;
    int b = blockIdx.z, h = blockIdx.y;
    int q0 = blockIdx.x * 64;
    int maxid = Ssz - num_targets[b];

    const size_t rstride = N_UVQK;
    const float* qbase = uvqk + (size_t)(b * Ssz) * rstride + 2048 + h * 128;
    const float* kbase = uvqk + (size_t)(b * Ssz) * rstride + 3072 + h * 128;
    const float* vbase = uvqk + (size_t)(b * Ssz) * rstride + 1024 + h * 128;

    {
        int r = tid >> 2, cb = (tid & 3) * 32;
        const float* src = qbase + (size_t)(q0 + r) * rstride + cb;
        #pragma unroll
        for (int x = 0; x < 8; x++) {
            float4 v = *(const float4*)(src + x * 4);
            QS(r, cb + x * 4 + 0) = f2tf32(v.x);
            QS(r, cb + x * 4 + 1) = f2tf32(v.y);
            QS(r, cb + x * 4 + 2) = f2tf32(v.z);
            QS(r, cb + x * 4 + 3) = f2tf32(v.w);
        }
    }

    int sWM = wid & 3, sWN = wid >> 2;
    int oWM = wid & 1, oWN = wid >> 1;

    float acc_o[2][4][4];
    #pragma unroll
    for (int i = 0; i < 2; i++)
        #pragma unroll
        for (int j = 0; j < 4; j++)
            #pragma unroll
            for (int q = 0; q < 4; q++) acc_o[i][j][q] = 0.f;

    int ldr = tid >> 2, ldc = (tid & 3) * 32;

    for (int k0 = 0; k0 <= q0; k0 += 64) {
        __syncthreads();
        {
            const float* ksrc = kbase + (size_t)(k0 + ldr) * rstride + ldc;
            const float* vsrc = vbase + (size_t)(k0 + ldr) * rstride + ldc;
            #pragma unroll
            for (int x = 0; x < 8; x++) {
                float4 kv = *(const float4*)(ksrc + x * 4);
                KS(ldr, ldc + x * 4 + 0) = f2tf32(kv.x);
                KS(ldr, ldc + x * 4 + 1) = f2tf32(kv.y);
                KS(ldr, ldc + x * 4 + 2) = f2tf32(kv.z);
                KS(ldr, ldc + x * 4 + 3) = f2tf32(kv.w);
            }
            #pragma unroll
            for (int x = 0; x < 8; x++) {
                float4 vv = *(const float4*)(vsrc + x * 4);
                VS(ldr, ldc + x * 4 + 0) = f2tf32(vv.x);
                VS(ldr, ldc + x * 4 + 1) = f2tf32(vv.y);
                VS(ldr, ldc + x * 4 + 2) = f2tf32(vv.z);
                VS(ldr, ldc + x * 4 + 3) = f2tf32(vv.w);
            }
        }
        __syncthreads();

        float acc_s[4][4];
        #pragma unroll
        for (int j = 0; j < 4; j++)
            #pragma unroll
            for (int q = 0; q < 4; q++) acc_s[j][q] = 0.f;

        #pragma unroll
        for (int ks = 0; ks < 16; ks++) {
            int kb = ks * 8;
            int m = sWM * 16 + gID;
            uint32_t a0 = QS(m, kb + tig);
            uint32_t a1 = QS(m + 8, kb + tig);
            uint32_t a2 = QS(m, kb + tig + 4);
            uint32_t a3 = QS(m + 8, kb + tig + 4);
            #pragma unroll
            for (int j = 0; j < 4; j++) {
                int n = sWN * 32 + j * 8 + gID;
                uint32_t b0 = KS(n, kb + tig);
                uint32_t b1 = KS(n, kb + tig + 4);
                mma_tf32(acc_s[j], a0, a1, a2, a3, b0, b1);
            }
        }

        {
            int rowL = sWM * 16 + gID;
            int qg0 = q0 + rowL;
            int qg1 = qg0 + 8;
            int idq0 = min(qg0, maxid);
            int idq1 = min(qg1, maxid);
            #pragma unroll
            for (int j = 0; j < 4; j++) {
                int colL = sWN * 32 + j * 8 + tig * 2;
                #pragma unroll
                for (int cc = 0; cc < 2; cc++) {
                    int kg = k0 + colL + cc;
                    int idk = min(kg, maxid);
                    float s0 = acc_s[j][cc] * ALPHA_SC;
                    float s1 = acc_s[j][cc + 2] * ALPHA_SC;
                    bool v0 = (qg0 == kg) || (idq0 > idk);
                    bool v1 = (qg1 == kg) || (idq1 > idk);
                    float w0 = v0 ? silu_f(s0) * INV_S : 0.f;
                    float w1 = v1 ? silu_f(s1) * INV_S : 0.f;
                    WS(rowL, colL + cc)     = f2tf32(w0);
                    WS(rowL + 8, colL + cc) = f2tf32(w1);
                }
            }
        }
        __syncthreads();

        #pragma unroll
        for (int ks = 0; ks < 8; ks++) {
            int kb = ks * 8;
            uint32_t af[2][4];
            #pragma unroll
            for (int i = 0; i < 2; i++) {
                int m = oWM * 32 + i * 16 + gID;
                af[i][0] = WS(m, kb + tig);
                af[i][1] = WS(m + 8, kb + tig);
                af[i][2] = WS(m, kb + tig + 4);
                af[i][3] = WS(m + 8, kb + tig + 4);
            }
            #pragma unroll
            for (int j = 0; j < 4; j++) {
                int n = oWN * 32 + j * 8 + gID;
                uint32_t b0 = VS(kb + tig, n);
                uint32_t b1 = VS(kb + tig + 4, n);
                #pragma unroll
                for (int i = 0; i < 2; i++)
                    mma_tf32(acc_o[i][j], af[i][0], af[i][1], af[i][2], af[i][3],
                             b0, b1);
            }
        }
    }

    #pragma unroll
    for (int i = 0; i < 2; i++) {
        int rowL = oWM * 32 + i * 16 + gID;
        size_t grow0 = (size_t)(b * Ssz + q0 + rowL) * Esz;
        size_t grow1 = (size_t)(b * Ssz + q0 + rowL + 8) * Esz;
        #pragma unroll
        for (int j = 0; j < 4; j++) {
            int col = h * 128 + oWN * 32 + j * 8 + tig * 2;
            *(float2*)&attn_out[grow0 + col] = make_float2(acc_o[i][j][0], acc_o[i][j][1]);
            *(float2*)&attn_out[grow1 + col] = make_float2(acc_o[i][j][2], acc_o[i][j][3]);
        }
    }
}

// ---------------- post-attention: LN(attn), gate, fill proj (tf32-rounded) --
__global__ __launch_bounds__(256) void postattn_kernel(
    const float* __restrict__ attn, const float* __restrict__ sc,
    const float* __restrict__ bi, float* __restrict__ proj)
{
    int row = blockIdx.x;
    int c = threadIdx.x * 4;
    const float* ar = attn + (size_t)row * Esz;
    float4 a = *(const float4*)&ar[c];
    float s  = a.x + a.y + a.z + a.w;
    float ss = a.x*a.x + a.y*a.y + a.z*a.z + a.w*a.w;
    blockReduce2(s, ss);
    float mu = s * (1.0f / Esz);
    float rs = rsqrtf(ss * (1.0f / Esz) - mu * mu + LN_EPS);
    float4 s4 = *(const float4*)&sc[c];
    float4 b4 = *(const float4*)&bi[c];
    float4 n;
    n.x = (a.x - mu) * rs * s4.x + b4.x;
    n.y = (a.y - mu) * rs * s4.y + b4.y;
    n.z = (a.z - mu) * rs * s4.z + b4.z;
    n.w = (a.w - mu) * rs * s4.w + b4.w;
    float* pr = proj + (size_t)row * N_PROJ;
    float4 u = *(const float4*)&pr[c];         // silu(u), already tf32-rounded
    float4 ar4;
    ar4.x = rnd32(a.x); ar4.y = rnd32(a.y); ar4.z = rnd32(a.z); ar4.w = rnd32(a.w);
    *(float4*)&pr[1024 + c] = ar4;
    float4 g;
    g.x = rnd32(u.x * n.x); g.y = rnd32(u.y * n.y);
    g.z = rnd32(u.z * n.z); g.w = rnd32(u.w * n.w);
    *(float4*)&pr[2048 + c] = g;
}

// ---------------- launch ----------------
extern "C" void kernel_launch(void* const* d_in, const int* in_sizes, int n_in,
                              void* d_out, int out_size)
{
    const float* x           = (const float*)d_in[0];
    const int*   num_targets = (const int*)  d_in[1];
    const float* uvqk_w      = (const float*)d_in[2];
    const float* uvqk_beta   = (const float*)d_in[3];
    const float* out_w       = (const float*)d_in[4];
    const float* in_scale    = (const float*)d_in[5];
    const float* in_bias     = (const float*)d_in[6];
    const float* out_scale   = (const float*)d_in[7];
    const float* out_bias    = (const float*)d_in[8];
    float* out = (float*)d_out;

    float *normx, *uvqk, *attn, *proj, *w1, *w2;
    cudaGetSymbolAddress((void**)&normx, g_normx);
    cudaGetSymbolAddress((void**)&uvqk,  g_uvqk);
    cudaGetSymbolAddress((void**)&attn,  g_attn);
    cudaGetSymbolAddress((void**)&proj,  g_proj);
    cudaGetSymbolAddress((void**)&w1,    g_w1);
    cudaGetSymbolAddress((void**)&w2,    g_w2);

    // idempotent, capture-safe; no static state
    cudaFuncSetAttribute(attn_tc_kernel,
                         cudaFuncAttributeMaxDynamicSharedMemorySize,
                         ATTN_SMEM_BYTES);
    cudaFuncSetAttribute(gemm_tf32_kernel,
                         cudaFuncAttributeMaxDynamicSharedMemorySize,
                         GEMM_SMEM_BYTES);

    // 0) pre-round weights to tf32 values
    round_w_kernel<<<(Esz * N_UVQK / 4 + 255) / 256, 256>>>(uvqk_w, w1, Esz * N_UVQK / 4);
    round_w_kernel<<<(N_PROJ * Esz / 4 + 255) / 256, 256>>>(out_w, w2, N_PROJ * Esz / 4);

    // 1) LayerNorm input (tf32-rounded output)
    ln_in_kernel<<<Mrows, 256>>>(x, in_scale, in_bias, normx);

    // 2) UVQK GEMM: (8192 x 1024) @ (1024 x 4096) + beta, silu(u) tap
    gemm_tf32_kernel<<<dim3(N_UVQK / 128, Mrows / 128), 256, GEMM_SMEM_BYTES>>>(
        normx, w1, uvqk, Mrows, N_UVQK, Esz, uvqk_beta, nullptr, proj);

    // 3) tensor-core attention (causal-skip, 64-row q tiles) -> attn
    attn_tc_kernel<<<dim3(Ssz / 64, Hsz, Bsz), 256, ATTN_SMEM_BYTES>>>(
        uvqk, num_targets, attn);

    // 4) LN(attn) + gate (tf32-rounded proj entries)
    postattn_kernel<<<Mrows, 256>>>(attn, out_scale, out_bias, proj);

    // 5) output GEMM with fused residual
    gemm_tf32_kernel<<<dim3(Esz / 128, Mrows / 128), 256, GEMM_SMEM_BYTES>>>(
        proj, w2, out, Mrows, Esz, N_PROJ, nullptr, x, nullptr);
}

// round 12
// speedup vs baseline: 1.5030x; 1.1286x over previous
#include <cuda_runtime.h>
#include <math.h>
#include <stdint.h>

// ---------------- problem constants ----------------
#define Bsz   4
#define Ssz   2048
#define Esz   1024
#define Hsz   8
#define Mrows (Bsz * Ssz)          // 8192
#define N_UVQK 4096
#define N_PROJ 3072
#define ALPHA_SC 0.08838834764831845f   // 1/sqrt(128)
#define INV_S    (1.0f / 2048.0f)
#define LN_EPS   1e-6f

// ---------------- scratch (device globals; no allocation allowed) -----------
__device__ float g_normx[(size_t)Mrows * Esz];    // 32 MB (tf32-rounded)
__device__ float g_uvqk [(size_t)Mrows * N_UVQK]; // 128 MB (tf32-rounded)
__device__ float g_attn [(size_t)Mrows * Esz];    // 32 MB (full fp32)
__device__ float g_proj [(size_t)Mrows * N_PROJ]; // 96 MB (tf32-rounded)
__device__ float g_w1   [(size_t)Esz * N_UVQK];   // 16 MB rounded uvqk_w
__device__ float g_w2   [(size_t)N_PROJ * Esz];   // 12 MB rounded out_w

// ---------------- helpers ----------------
__device__ __forceinline__ uint32_t f2tf32(float x) {
    uint32_t r;
    asm("cvt.rna.tf32.f32 %0, %1;" : "=r"(r) : "f"(x));
    return r;
}
__device__ __forceinline__ float rnd32(float x) {
    return __uint_as_float(f2tf32(x));
}

__device__ __forceinline__ void mma_tf32(float* d,
    uint32_t a0, uint32_t a1, uint32_t a2, uint32_t a3,
    uint32_t b0, uint32_t b1)
{
    asm volatile(
        "mma.sync.aligned.m16n8k8.row.col.f32.tf32.tf32.f32 "
        "{%0,%1,%2,%3}, {%4,%5,%6,%7}, {%8,%9}, {%0,%1,%2,%3};\n"
        : "+f"(d[0]), "+f"(d[1]), "+f"(d[2]), "+f"(d[3])
        : "r"(a0), "r"(a1), "r"(a2), "r"(a3), "r"(b0), "r"(b1));
}

__device__ __forceinline__ float silu_f(float x) {
    return x / (1.0f + expf(-x));
}

__device__ __forceinline__ uint32_t smem_u32(const void* p) {
    uint32_t a;
    asm("{ .reg .u64 t; cvta.to.shared.u64 t, %1; cvt.u32.u64 %0, t; }"
        : "=r"(a) : "l"(p));
    return a;
}

__device__ __forceinline__ void cp_async16(uint32_t dst, const void* src) {
    asm volatile("cp.async.cg.shared.global [%0], [%1], 16;\n"
                 :: "r"(dst), "l"(src));
}
#define CP_COMMIT()  asm volatile("cp.async.commit_group;\n" ::: "memory")
#define CP_WAIT1()   asm volatile("cp.async.wait_group 1;\n" ::: "memory")

__device__ __forceinline__ void blockReduce2(float& a, float& b) {
    #pragma unroll
    for (int off = 16; off > 0; off >>= 1) {
        a += __shfl_down_sync(0xffffffffu, a, off);
        b += __shfl_down_sync(0xffffffffu, b, off);
    }
    __shared__ float sa[8], sb[8];
    __shared__ float ra, rb;
    int w = threadIdx.x >> 5, l = threadIdx.x & 31;
    if (l == 0) { sa[w] = a; sb[w] = b; }
    __syncthreads();
    if (threadIdx.x == 0) {
        float ta = 0.f, tb = 0.f;
        #pragma unroll
        for (int i = 0; i < 8; i++) { ta += sa[i]; tb += sb[i]; }
        ra = ta; rb = tb;
    }
    __syncthreads();
    a = ra; b = rb;
}

// ---------------- tf32 pre-round of weights ----------------
__global__ __launch_bounds__(256) void round_w_kernel(
    const float* __restrict__ src, float* __restrict__ dst, int n4)
{
    int i = (blockIdx.x * 256 + threadIdx.x);
    if (i < n4) {
        float4 v = *(const float4*)(src + (size_t)i * 4);
        v.x = rnd32(v.x); v.y = rnd32(v.y); v.z = rnd32(v.z); v.w = rnd32(v.w);
        *(float4*)(dst + (size_t)i * 4) = v;
    }
}

// ---------------- LayerNorm on input x -> g_normx (tf32-rounded) -----------
__global__ __launch_bounds__(256) void ln_in_kernel(
    const float* __restrict__ x, const float* __restrict__ sc,
    const float* __restrict__ bi, float* __restrict__ out)
{
    int row = blockIdx.x;
    int c = threadIdx.x * 4;
    const float* xr = x + (size_t)row * Esz;
    float4 v = *(const float4*)&xr[c];
    float s  = v.x + v.y + v.z + v.w;
    float ss = v.x*v.x + v.y*v.y + v.z*v.z + v.w*v.w;
    blockReduce2(s, ss);
    float mu = s * (1.0f / Esz);
    float rs = rsqrtf(ss * (1.0f / Esz) - mu * mu + LN_EPS);
    float4 s4 = *(const float4*)&sc[c];
    float4 b4 = *(const float4*)&bi[c];
    float4 o;
    o.x = rnd32((v.x - mu) * rs * s4.x + b4.x);
    o.y = rnd32((v.y - mu) * rs * s4.y + b4.y);
    o.z = rnd32((v.z - mu) * rs * s4.z + b4.z);
    o.w = rnd32((v.w - mu) * rs * s4.w + b4.w);
    *(float4*)&out[(size_t)row * Esz + c] = o;
}

// ---------------- tf32 mma.sync GEMM, cp.async 3-stage ----------------------
// A: MxK row-major fp32 (values already tf32-rounded). B: KxN likewise.
// Block tile 128x128, kTile 16, 3-stage cp.async pipeline.
// round_c != 0: store C values tf32-rounded (for uvqk consumed by attention).
#define GSTG_WORDS 4672
#define GEMM_SMEM_BYTES (3 * GSTG_WORDS * 4)   // 56064 B

__global__ __launch_bounds__(256, 2) void gemm_tf32_kernel(
    const float* __restrict__ A, const float* __restrict__ Bm,
    float* __restrict__ C, int M, int N, int K,
    const float* __restrict__ bias, const float* __restrict__ resid,
    float* __restrict__ silu_dst, int round_c)
{
    extern __shared__ __align__(16) uint32_t gsm[];
    uint32_t sbase = smem_u32(gsm);

    int tid = threadIdx.x;
    int wid = tid >> 5, lane = tid & 31;
    int gID = lane >> 2, tig = lane & 3;
    int warpM = wid & 1, warpN = wid >> 1;
    int bx = blockIdx.x, by = blockIdx.y;

    int arow = tid >> 1, acol = (tid & 1) * 8;
    int brow = tid >> 4, bcol = (tid & 15) * 8;
    const float* Abase = A + (size_t)(by * 128 + arow) * K + acol;
    const float* Bbase = Bm + (size_t)brow * N + bx * 128 + bcol;

    int nIter = K >> 4;

    auto issue_stage = [&](int c) {
        int s = c - (c / 3) * 3;
        uint32_t ab = sbase + (uint32_t)(s * GSTG_WORDS) * 4;
        uint32_t bb = ab + 2560 * 4;
        const float* ag = Abase + c * 16;
        cp_async16(ab + (uint32_t)(arow * 20 + acol) * 4, ag);
        cp_async16(ab + (uint32_t)(arow * 20 + acol + 4) * 4, ag + 4);
        const float* bg = Bbase + (size_t)(c * 16) * N;
        cp_async16(bb + (uint32_t)(brow * 132 + bcol) * 4, bg);
        cp_async16(bb + (uint32_t)(brow * 132 + bcol + 4) * 4, bg + 4);
    };

    float acc[4][4][4];
    #pragma unroll
    for (int i = 0; i < 4; i++)
        #pragma unroll
        for (int j = 0; j < 4; j++)
            #pragma unroll
            for (int q = 0; q < 4; q++) acc[i][j][q] = 0.f;

    issue_stage(0); CP_COMMIT();
    issue_stage(1); CP_COMMIT();

    for (int c = 0; c < nIter; c++) {
        CP_WAIT1();            // stage c resident
        __syncthreads();       // all warps done with stage c-1 compute; c visible
        if (c + 2 < nIter) issue_stage(c + 2);
        CP_COMMIT();           // always commit (empty group at tail keeps count)

        int s = c - (c / 3) * 3;
        const uint32_t* As = gsm + s * GSTG_WORDS;
        const uint32_t* Bs = As + 2560;
        #pragma unroll
        for (int ks = 0; ks < 2; ks++) {
            int kb = ks * 8;
            uint32_t af[4][4], bf[4][2];
            #pragma unroll
            for (int i = 0; i < 4; i++) {
                int m = warpM * 64 + i * 16 + gID;
                af[i][0] = As[m * 20 + kb + tig];
                af[i][1] = As[(m + 8) * 20 + kb + tig];
                af[i][2] = As[m * 20 + kb + tig + 4];
                af[i][3] = As[(m + 8) * 20 + kb + tig + 4];
            }
            #pragma unroll
            for (int j = 0; j < 4; j++) {
                int n = warpN * 32 + j * 8 + gID;
                bf[j][0] = Bs[(kb + tig) * 132 + n];
                bf[j][1] = Bs[(kb + tig + 4) * 132 + n];
            }
            #pragma unroll
            for (int i = 0; i < 4; i++)
                #pragma unroll
                for (int j = 0; j < 4; j++)
                    mma_tf32(acc[i][j], af[i][0], af[i][1], af[i][2], af[i][3],
                             bf[j][0], bf[j][1]);
        }
    }

    // epilogue
    bool siluTile = (silu_dst != nullptr) && (bx * 128 < 1024);
    #pragma unroll
    for (int i = 0; i < 4; i++) {
        int r0 = by * 128 + warpM * 64 + i * 16 + gID;
        #pragma unroll
        for (int j = 0; j < 4; j++) {
            int cg = bx * 128 + warpN * 32 + j * 8 + tig * 2;
            float v0 = acc[i][j][0], v1 = acc[i][j][1];
            float v2 = acc[i][j][2], v3 = acc[i][j][3];
            if (bias) {
                float b0 = bias[cg], b1 = bias[cg + 1];
                v0 += b0; v1 += b1; v2 += b0; v3 += b1;
            }
            size_t o0 = (size_t)r0 * N + cg;
            size_t o1 = (size_t)(r0 + 8) * N + cg;
            if (resid) {
                v0 += resid[o0]; v1 += resid[o0 + 1];
                v2 += resid[o1]; v3 += resid[o1 + 1];
            }
            if (round_c) {
                *(float2*)&C[o0] = make_float2(rnd32(v0), rnd32(v1));
                *(float2*)&C[o1] = make_float2(rnd32(v2), rnd32(v3));
            } else {
                *(float2*)&C[o0] = make_float2(v0, v1);
                *(float2*)&C[o1] = make_float2(v2, v3);
            }
            if (siluTile) {
                size_t p0 = (size_t)r0 * N_PROJ + cg;
                size_t p1 = (size_t)(r0 + 8) * N_PROJ + cg;
                *(float2*)&silu_dst[p0] =
                    make_float2(rnd32(silu_f(v0)), rnd32(silu_f(v1)));
                *(float2*)&silu_dst[p1] =
                    make_float2(rnd32(silu_f(v2)), rnd32(silu_f(v3)));
            }
        }
    }
}

// ---------------- cp.async-pipelined tensor-core attention ------------------
// block = (b, h, 64 q rows). 256 threads / 8 warps. K-tiles of 64, causal skip.
// uvqk values are pre-rounded to tf32, so tiles are loaded as raw bytes via
// cp.async with one-tile lookahead (double-buffered K/V stages).
// smem words: Qs[64][132]@0   K stages @8448,@16896
//             V stages @25344,@33792   Ws[64][68]@42240
// total 46592 words = 186368 B
#define AQ(r,c)    sm[(r) * 132 + (c)]
#define AK(s,r,c)  sm[8448 + (s) * 8448 + (r) * 132 + (c)]
#define AV(s,r,c)  sm[25344 + (s) * 8448 + (r) * 132 + (c)]
#define AW(r,c)    sm[42240 + (r) * 68 + (c)]
#define ATTN_SMEM_BYTES (46592 * 4)

__global__ __launch_bounds__(256) void attn_tc_kernel(
    const float* __restrict__ uvqk, const int* __restrict__ num_targets,
    float* __restrict__ attn_out)
{
    extern __shared__ uint32_t sm[];
    uint32_t sbase = smem_u32(sm);
    int tid = threadIdx.x;
    int wid = tid >> 5, lane = tid & 31;
    int gID = lane >> 2, tig = lane & 3;
    int b = blockIdx.z, h = blockIdx.y;
    int q0 = blockIdx.x * 64;
    int maxid = Ssz - num_targets[b];

    const size_t rstride = N_UVQK;
    const float* qbase = uvqk + (size_t)(b * Ssz) * rstride + 2048 + h * 128;
    const float* kbase = uvqk + (size_t)(b * Ssz) * rstride + 3072 + h * 128;
    const float* vbase = uvqk + (size_t)(b * Ssz) * rstride + 1024 + h * 128;

    int ldr = tid >> 2, ldc = (tid & 3) * 32;

    // Q tile via cp.async (group 0)
    {
        const float* qsrc = qbase + (size_t)(q0 + ldr) * rstride + ldc;
        #pragma unroll
        for (int x = 0; x < 8; x++)
            cp_async16(sbase + (uint32_t)(ldr * 132 + ldc + x * 4) * 4,
                       qsrc + x * 4);
    }
    CP_COMMIT();

    auto issue_kv = [&](int t) {
        int s = t & 1;
        const float* ksrc = kbase + (size_t)(t * 64 + ldr) * rstride + ldc;
        const float* vsrc = vbase + (size_t)(t * 64 + ldr) * rstride + ldc;
        uint32_t kdst = sbase + (uint32_t)(8448 + s * 8448 + ldr * 132 + ldc) * 4;
        uint32_t vdst = sbase + (uint32_t)(25344 + s * 8448 + ldr * 132 + ldc) * 4;
        #pragma unroll
        for (int x = 0; x < 8; x++) {
            cp_async16(kdst + x * 16, ksrc + x * 4);
            cp_async16(vdst + x * 16, vsrc + x * 4);
        }
    };

    issue_kv(0); CP_COMMIT();      // group 1

    int sWM = wid & 3, sWN = wid >> 2;
    int oWM = wid & 1, oWN = wid >> 1;

    float acc_o[2][4][4];
    #pragma unroll
    for (int i = 0; i < 2; i++)
        #pragma unroll
        for (int j = 0; j < 4; j++)
            #pragma unroll
            for (int q = 0; q < 4; q++) acc_o[i][j][q] = 0.f;

    int ntiles = q0 / 64 + 1;

    for (int t = 0; t < ntiles; t++) {
        int s = t & 1;
        __syncthreads();   // everyone done with stage s from iter t-2 and Ws
        if (t + 1 < ntiles) issue_kv(t + 1);
        CP_COMMIT();       // always commit (empty tail groups keep the count)
        CP_WAIT1();        // tile t (and Q) resident; t+1 may be in flight
        __syncthreads();   // cross-thread visibility of cp.async data

        // scores: S(64x64) = Q(64x128) @ K^T
        float acc_s[4][4];
        #pragma unroll
        for (int j = 0; j < 4; j++)
            #pragma unroll
            for (int q = 0; q < 4; q++) acc_s[j][q] = 0.f;

        #pragma unroll
        for (int ks = 0; ks < 16; ks++) {
            int kb = ks * 8;
            int m = sWM * 16 + gID;
            uint32_t a0 = AQ(m, kb + tig);
            uint32_t a1 = AQ(m + 8, kb + tig);
            uint32_t a2 = AQ(m, kb + tig + 4);
            uint32_t a3 = AQ(m + 8, kb + tig + 4);
            #pragma unroll
            for (int j = 0; j < 4; j++) {
                int n = sWN * 32 + j * 8 + gID;
                uint32_t b0 = AK(s, n, kb + tig);
                uint32_t b1 = AK(s, n, kb + tig + 4);
                mma_tf32(acc_s[j], a0, a1, a2, a3, b0, b1);
            }
        }

        // mask + silu -> Ws
        {
            int k0 = t * 64;
            int rowL = sWM * 16 + gID;
            int qg0 = q0 + rowL;
            int qg1 = qg0 + 8;
            int idq0 = min(qg0, maxid);
            int idq1 = min(qg1, maxid);
            #pragma unroll
            for (int j = 0; j < 4; j++) {
                int colL = sWN * 32 + j * 8 + tig * 2;
                #pragma unroll
                for (int cc = 0; cc < 2; cc++) {
                    int kg = k0 + colL + cc;
                    int idk = min(kg, maxid);
                    float s0 = acc_s[j][cc] * ALPHA_SC;
                    float s1 = acc_s[j][cc + 2] * ALPHA_SC;
                    bool v0 = (qg0 == kg) || (idq0 > idk);
                    bool v1 = (qg1 == kg) || (idq1 > idk);
                    float w0 = v0 ? silu_f(s0) * INV_S : 0.f;
                    float w1 = v1 ? silu_f(s1) * INV_S : 0.f;
                    AW(rowL, colL + cc)     = f2tf32(w0);
                    AW(rowL + 8, colL + cc) = f2tf32(w1);
                }
            }
        }
        __syncthreads();

        // O += Ws(64x64) @ V(64x128)
        #pragma unroll
        for (int ks = 0; ks < 8; ks++) {
            int kb = ks * 8;
            uint32_t af[2][4];
            #pragma unroll
            for (int i = 0; i < 2; i++) {
                int m = oWM * 32 + i * 16 + gID;
                af[i][0] = AW(m, kb + tig);
                af[i][1] = AW(m + 8, kb + tig);
                af[i][2] = AW(m, kb + tig + 4);
                af[i][3] = AW(m + 8, kb + tig + 4);
            }
            #pragma unroll
            for (int j = 0; j < 4; j++) {
                int n = oWN * 32 + j * 8 + gID;
                uint32_t b0 = AV(s, kb + tig, n);
                uint32_t b1 = AV(s, kb + tig + 4, n);
                #pragma unroll
                for (int i = 0; i < 2; i++)
                    mma_tf32(acc_o[i][j], af[i][0], af[i][1], af[i][2], af[i][3],
                             b0, b1);
            }
        }
    }

    #pragma unroll
    for (int i = 0; i < 2; i++) {
        int rowL = oWM * 32 + i * 16 + gID;
        size_t grow0 = (size_t)(b * Ssz + q0 + rowL) * Esz;
        size_t grow1 = (size_t)(b * Ssz + q0 + rowL + 8) * Esz;
        #pragma unroll
        for (int j = 0; j < 4; j++) {
            int col = h * 128 + oWN * 32 + j * 8 + tig * 2;
            *(float2*)&attn_out[grow0 + col] = make_float2(acc_o[i][j][0], acc_o[i][j][1]);
            *(float2*)&attn_out[grow1 + col] = make_float2(acc_o[i][j][2], acc_o[i][j][3]);
        }
    }
}

// ---------------- post-attention: LN(attn), gate, fill proj (tf32-rounded) --
__global__ __launch_bounds__(256) void postattn_kernel(
    const float* __restrict__ attn, const float* __restrict__ sc,
    const float* __restrict__ bi, float* __restrict__ proj)
{
    int row = blockIdx.x;
    int c = threadIdx.x * 4;
    const float* ar = attn + (size_t)row * Esz;
    float4 a = *(const float4*)&ar[c];
    float s  = a.x + a.y + a.z + a.w;
    float ss = a.x*a.x + a.y*a.y + a.z*a.z + a.w*a.w;
    blockReduce2(s, ss);
    float mu = s * (1.0f / Esz);
    float rs = rsqrtf(ss * (1.0f / Esz) - mu * mu + LN_EPS);
    float4 s4 = *(const float4*)&sc[c];
    float4 b4 = *(const float4*)&bi[c];
    float4 n;
    n.x = (a.x - mu) * rs * s4.x + b4.x;
    n.y = (a.y - mu) * rs * s4.y + b4.y;
    n.z = (a.z - mu) * rs * s4.z + b4.z;
    n.w = (a.w - mu) * rs * s4.w + b4.w;
    float* pr = proj + (size_t)row * N_PROJ;
    float4 u = *(const float4*)&pr[c];         // silu(u), already tf32-rounded
    float4 ar4;
    ar4.x = rnd32(a.x); ar4.y = rnd32(a.y); ar4.z = rnd32(a.z); ar4.w = rnd32(a.w);
    *(float4*)&pr[1024 + c] = ar4;
    float4 g;
    g.x = rnd32(u.x * n.x); g.y = rnd32(u.y * n.y);
    g.z = rnd32(u.z * n.z); g.w = rnd32(u.w * n.w);
    *(float4*)&pr[2048 + c] = g;
}

// ---------------- launch ----------------
extern "C" void kernel_launch(void* const* d_in, const int* in_sizes, int n_in,
                              void* d_out, int out_size)
{
    const float* x           = (const float*)d_in[0];
    const int*   num_targets = (const int*)  d_in[1];
    const float* uvqk_w      = (const float*)d_in[2];
    const float* uvqk_beta   = (const float*)d_in[3];
    const float* out_w       = (const float*)d_in[4];
    const float* in_scale    = (const float*)d_in[5];
    const float* in_bias     = (const float*)d_in[6];
    const float* out_scale   = (const float*)d_in[7];
    const float* out_bias    = (const float*)d_in[8];
    float* out = (float*)d_out;

    float *normx, *uvqk, *attn, *proj, *w1, *w2;
    cudaGetSymbolAddress((void**)&normx, g_normx);
    cudaGetSymbolAddress((void**)&uvqk,  g_uvqk);
    cudaGetSymbolAddress((void**)&attn,  g_attn);
    cudaGetSymbolAddress((void**)&proj,  g_proj);
    cudaGetSymbolAddress((void**)&w1,    g_w1);
    cudaGetSymbolAddress((void**)&w2,    g_w2);

    // idempotent, capture-safe; no static state
    cudaFuncSetAttribute(attn_tc_kernel,
                         cudaFuncAttributeMaxDynamicSharedMemorySize,
                         ATTN_SMEM_BYTES);
    cudaFuncSetAttribute(gemm_tf32_kernel,
                         cudaFuncAttributeMaxDynamicSharedMemorySize,
                         GEMM_SMEM_BYTES);

    // 0) pre-round weights to tf32 values
    round_w_kernel<<<(Esz * N_UVQK / 4 + 255) / 256, 256>>>(uvqk_w, w1, Esz * N_UVQK / 4);
    round_w_kernel<<<(N_PROJ * Esz / 4 + 255) / 256, 256>>>(out_w, w2, N_PROJ * Esz / 4);

    // 1) LayerNorm input (tf32-rounded output)
    ln_in_kernel<<<Mrows, 256>>>(x, in_scale, in_bias, normx);

    // 2) UVQK GEMM: + beta, silu(u) tap, C stored tf32-rounded for attention
    gemm_tf32_kernel<<<dim3(N_UVQK / 128, Mrows / 128), 256, GEMM_SMEM_BYTES>>>(
        normx, w1, uvqk, Mrows, N_UVQK, Esz, uvqk_beta, nullptr, proj, 1);

    // 3) cp.async-pipelined tensor-core attention (causal-skip) -> attn
    attn_tc_kernel<<<dim3(Ssz / 64, Hsz, Bsz), 256, ATTN_SMEM_BYTES>>>(
        uvqk, num_targets, attn);

    // 4) LN(attn) + gate (tf32-rounded proj entries)
    postattn_kernel<<<Mrows, 256>>>(attn, out_scale, out_bias, proj);

    // 5) output GEMM with fused residual (exact fp32 output)
    gemm_tf32_kernel<<<dim3(Esz / 128, Mrows / 128), 256, GEMM_SMEM_BYTES>>>(
        proj, w2, out, Mrows, Esz, N_PROJ, nullptr, x, nullptr, 0);
}